// round 13
// baseline (speedup 1.0000x reference)
#include <cuda_runtime.h>
#include <cuda_fp16.h>
#include <cstdint>

#define B_  2
#define S_  2048
#define H_  768
#define NH_ 12
#define HD_ 64
#define KB_ 12          // 768 / 64 k-chunks

// fp16 projections: [bh][s][64]. Q pre-scaled by log2(e)/8.
__device__ __align__(16) __half g_qh[(size_t)B_ * NH_ * S_ * 64];
__device__ __align__(16) __half g_kh[(size_t)B_ * NH_ * S_ * 64];
__device__ __align__(16) __half g_vh[(size_t)B_ * NH_ * S_ * 64];
// fp16 GEMM inputs:
__device__ __align__(16) __half g_xh[(size_t)B_ * S_ * KB_ * 64];
__device__ __align__(16) __half g_wh[(size_t)3 * H_ * KB_ * 64];

// ============================ PTX helpers ==================================
__device__ __forceinline__ uint32_t smem_u32(const void* p) {
    uint32_t a;
    asm("{ .reg .u64 t; cvta.to.shared.u64 t, %1; cvt.u32.u64 %0, t; }"
        : "=r"(a) : "l"(p));
    return a;
}
__device__ __forceinline__ void cpasync16(uint32_t dst, const void* src) {
    asm volatile("cp.async.cg.shared.global [%0], [%1], 16;"
                 :: "r"(dst), "l"(src) : "memory");
}
#define CP_COMMIT() asm volatile("cp.async.commit_group;" ::: "memory")
#define CP_WAIT0()  asm volatile("cp.async.wait_group 0;" ::: "memory")
#define CP_WAIT1()  asm volatile("cp.async.wait_group 1;" ::: "memory")
#define CP_WAIT2()  asm volatile("cp.async.wait_group 2;" ::: "memory")

__device__ __forceinline__ void ldsm4(uint32_t r[4], uint32_t addr) {
    asm volatile("ldmatrix.sync.aligned.m8n8.x4.shared.b16 {%0,%1,%2,%3}, [%4];"
        : "=r"(r[0]), "=r"(r[1]), "=r"(r[2]), "=r"(r[3]) : "r"(addr));
}
__device__ __forceinline__ void ldsm4t(uint32_t r[4], uint32_t addr) {
    asm volatile("ldmatrix.sync.aligned.m8n8.x4.trans.shared.b16 {%0,%1,%2,%3}, [%4];"
        : "=r"(r[0]), "=r"(r[1]), "=r"(r[2]), "=r"(r[3]) : "r"(addr));
}
// fp16 MMA, fp32 accumulate
__device__ __forceinline__ void mma16816h(float c[4], const uint32_t a[4],
                                          uint32_t b0, uint32_t b1) {
    asm volatile("mma.sync.aligned.m16n8k16.row.col.f32.f16.f16.f32 "
        "{%0,%1,%2,%3}, {%4,%5,%6,%7}, {%8,%9}, {%0,%1,%2,%3};"
        : "+f"(c[0]), "+f"(c[1]), "+f"(c[2]), "+f"(c[3])
        : "r"(a[0]), "r"(a[1]), "r"(a[2]), "r"(a[3]), "r"(b0), "r"(b1));
}
// pack two fp32 -> f16x2 (first arg -> bits [15:0])
__device__ __forceinline__ uint32_t packh(float lo, float hi) {
    uint32_t r; asm("cvt.rn.f16x2.f32 %0, %1, %2;" : "=r"(r) : "f"(hi), "f"(lo));
    return r;
}
// packed fp16x2 exp2
__device__ __forceinline__ uint32_t ex2h2(uint32_t x) {
    uint32_t y; asm("ex2.approx.f16x2 %0, %1;" : "=r"(y) : "r"(x)); return y;
}
// packed fp16x2 add
__device__ __forceinline__ uint32_t hadd2(uint32_t a, uint32_t b) {
    uint32_t y; asm("add.f16x2 %0, %1, %2;" : "=r"(y) : "r"(a), "r"(b)); return y;
}
// unpack f16x2 -> two fp32
__device__ __forceinline__ float2 h22f2(uint32_t h) {
    float lo, hi;
    asm("{ .reg .f16 l, u; mov.b32 {l, u}, %2;\n\t"
        "cvt.f32.f16 %0, l; cvt.f32.f16 %1, u; }"
        : "=f"(lo), "=f"(hi) : "r"(h));
    return make_float2(lo, hi);
}
// 128B rows (64 fp16), 8 chunks of 16B, XOR swizzle -> conflict-free ldmatrix
__device__ __forceinline__ uint32_t swa8(int row, int chunk) {
    return (uint32_t)(row * 128 + ((chunk ^ (row & 7)) << 4));
}

// ---------------------------------------------------------------------------
// Fused conversion kernel.
// blocks [0, 1536): conv_x  X fp32 [4096][768] -> g_xh fp16 [m][kb][64]
//                   (8 values per thread: 2 float4 loads -> 1 uint4 store)
// blocks [1536, 1968): conv_w  W fp32 -> g_wh fp16 [which][n][kb][64] (transp)
// ---------------------------------------------------------------------------
#define CVX_BLOCKS 1536

__global__ __launch_bounds__(256) void conv_kernel(
    const float* __restrict__ X,
    const float* __restrict__ Wq, const float* __restrict__ Wk,
    const float* __restrict__ Wv)
{
    __shared__ float T[64][65];
    const int tid = threadIdx.x;

    if (blockIdx.x < CVX_BLOCKS) {
        const int t = blockIdx.x * 256 + tid;      // 393216 threads
        const int m = t / 96, r = t % 96;
        const int kb = r >> 3, p8 = (r & 7) * 8;
        const float* src = X + (size_t)m * H_ + kb * 64 + p8;
        float4 x0 = *(const float4*)(src);
        float4 x1 = *(const float4*)(src + 4);
        uint4 o;
        o.x = packh(x0.x, x0.y);
        o.y = packh(x0.z, x0.w);
        o.z = packh(x1.x, x1.y);
        o.w = packh(x1.z, x1.w);
        *(uint4*)(g_xh + ((size_t)m * KB_ + kb) * 64 + p8) = o;
        return;
    }

    const int i = blockIdx.x - CVX_BLOCKS;     // 432 blocks
    const int kb = i % KB_;
    const int ng = (i / KB_) % 12;
    const int which = i / (KB_ * 12);
    const float* W = (which == 0) ? Wq : (which == 1) ? Wk : Wv;

    #pragma unroll
    for (int j = 0; j < 16; j++) {
        int idx = tid + 256 * j;
        int r = idx >> 6, c = idx & 63;
        T[r][c] = W[(size_t)(kb * 64 + r) * H_ + ng * 64 + c];
    }
    __syncthreads();

    const int n  = tid >> 2;
    const int jb = tid & 3;
    uint32_t* dst = (uint32_t*)(g_wh +
        (((size_t)which * H_ + ng * 64 + n) * KB_ + kb) * 64);
    #pragma unroll
    for (int j = 0; j < 8; j++) {
        int k2 = jb * 8 + j;
        dst[k2] = packh(T[2 * k2][n], T[2 * k2 + 1][n]);
    }
}

// ---------------------------------------------------------------------------
// fp16 HMMA QKV GEMM: 256 thr (8 warps, 4m x 2n), tile 128m x 128n (2 heads),
// 64-k chunks triple-buffered. smem 3 x (A 16KB + B 16KB) = 96KB, 2 CTAs/SM.
// ---------------------------------------------------------------------------
#define GSM_TOT 98304
#define GBUF    32768

__global__ void __launch_bounds__(256, 2) qkv_mma_kernel(
    const float* __restrict__ bq, const float* __restrict__ bk,
    const float* __restrict__ bv)
{
    extern __shared__ char sm[];
    const uint32_t smb = smem_u32(sm);

    const int tid = threadIdx.x;
    const int l = tid & 31, w = tid >> 5;
    const int wm = w & 3, wn = w >> 2;
    const int which = blockIdx.z;
    const int m0 = blockIdx.y * 128;
    const int n0 = blockIdx.x * 128;

    const __half* Ag = g_xh + (size_t)m0 * KB_ * 64;
    const __half* Bg = g_wh + ((size_t)which * H_ + n0) * KB_ * 64;

    float s[2][8][4];
    #pragma unroll
    for (int mt = 0; mt < 2; mt++)
        #pragma unroll
        for (int nt = 0; nt < 8; nt++)
            #pragma unroll
            for (int j = 0; j < 4; j++) s[mt][nt][j] = 0.0f;

    const int arow0 = 32 * wm + (l & 15);
    const int achnk = l >> 4;
    const int krow  = 64 * wn + (l & 7) + ((l >> 4) << 3);
    const int kchnk = (l >> 3) & 1;

    #pragma unroll
    for (int pb = 0; pb < 2; pb++) {
        const uint32_t off = (uint32_t)(pb * GBUF);
        #pragma unroll
        for (int i = 0; i < 4; i++) {
            int idx = tid + 256 * i;
            int r = idx >> 3, ch = idx & 7;
            cpasync16(smb + off + swa8(r, ch),
                      Ag + ((size_t)r * KB_ + pb) * 64 + ch * 8);
        }
        #pragma unroll
        for (int i = 0; i < 4; i++) {
            int idx = tid + 256 * i;
            int r = idx >> 3, ch = idx & 7;
            cpasync16(smb + off + 16384 + swa8(r, ch),
                      Bg + ((size_t)r * KB_ + pb) * 64 + ch * 8);
        }
        CP_COMMIT();
    }

    for (int kb = 0; kb < KB_; kb++) {
        CP_WAIT1();
        __syncthreads();
        if (kb + 2 < KB_) {
            const uint32_t off = (uint32_t)(((kb + 2) % 3) * GBUF);
            #pragma unroll
            for (int i = 0; i < 4; i++) {
                int idx = tid + 256 * i;
                int r = idx >> 3, ch = idx & 7;
                cpasync16(smb + off + swa8(r, ch),
                          Ag + ((size_t)r * KB_ + kb + 2) * 64 + ch * 8);
            }
            #pragma unroll
            for (int i = 0; i < 4; i++) {
                int idx = tid + 256 * i;
                int r = idx >> 3, ch = idx & 7;
                cpasync16(smb + off + 16384 + swa8(r, ch),
                          Bg + ((size_t)r * KB_ + kb + 2) * 64 + ch * 8);
            }
        }
        CP_COMMIT();

        const uint32_t smA = smb + (uint32_t)((kb % 3) * GBUF);
        const uint32_t smB = smA + 16384;

        #pragma unroll
        for (int ks = 0; ks < 4; ks++) {
            uint32_t a[2][4], bb[4][4];
            #pragma unroll
            for (int mt = 0; mt < 2; mt++)
                ldsm4(a[mt], smA + swa8(arow0 + 16 * mt, ks * 2 + achnk));
            #pragma unroll
            for (int bt = 0; bt < 4; bt++)
                ldsm4(bb[bt], smB + swa8(16 * bt + krow, ks * 2 + kchnk));
            #pragma unroll
            for (int mt = 0; mt < 2; mt++)
                #pragma unroll
                for (int bt = 0; bt < 4; bt++) {
                    mma16816h(s[mt][2 * bt],     a[mt], bb[bt][0], bb[bt][1]);
                    mma16816h(s[mt][2 * bt + 1], a[mt], bb[bt][2], bb[bt][3]);
                }
        }
    }

    // ---- epilogue: +bias, (Q: *log2e/8), fp16 pack, store [bh][s][64] ----
    const float* bias = (which == 0) ? bq : (which == 1) ? bk : bv;
    __half* Gp = (which == 0) ? g_qh : (which == 1) ? g_kh : g_vh;
    const float sc = (which == 0) ? 0.18033688011112042f : 1.0f;

    const int head = 2 * blockIdx.x + wn;
    #pragma unroll
    for (int mt = 0; mt < 2; mt++) {
        const int r0 = m0 + 32 * wm + 16 * mt + (l >> 2);
        const int b  = r0 >> 11;
        const int s0 = r0 & (S_ - 1);
        const int bh_ = b * NH_ + head;
        uint32_t* d0 = (uint32_t*)(Gp + ((size_t)bh_ * S_ + s0) * 64);
        uint32_t* d1 = (uint32_t*)(Gp + ((size_t)bh_ * S_ + s0 + 8) * 64);
        #pragma unroll
        for (int nt = 0; nt < 8; nt++) {
            const int c0 = 8 * nt + 2 * (l & 3);
            const float b0 = __ldg(bias + head * 64 + c0);
            const float b1 = __ldg(bias + head * 64 + c0 + 1);
            d0[c0 >> 1] = packh((s[mt][nt][0] + b0) * sc, (s[mt][nt][1] + b1) * sc);
            d1[c0 >> 1] = packh((s[mt][nt][2] + b0) * sc, (s[mt][nt][3] + b1) * sc);
        }
    }
}

// ---------------------------------------------------------------------------
// fp16 HMMA flash attention v5: q-tile 128/CTA (2 sets of 64), kv-buffer 128
// in two 64-kv sub-steps, K/V fragments shared across q-sets, f16x2 exp,
// row-sums via HADD2 trees (off the tensor pipe).
// smem: Q 16KB + 3 x 32KB = 112KB; 2 CTAs/SM.
// ---------------------------------------------------------------------------
#define SMQ   0
#define SMKV  16384
#define SMTOT 114688
#define NT_   (S_ / 128)

__global__ void __launch_bounds__(128, 2) attn_kernel(float* __restrict__ out)
{
    extern __shared__ char sm[];
    const uint32_t smb = smem_u32(sm);
    const uint32_t smq = smb + SMQ;

    const int tid = threadIdx.x;
    const int l = tid & 31, w = tid >> 5;
    const int head = blockIdx.y, b = blockIdx.z;
    const int bh = b * NH_ + head;
    const int q0 = blockIdx.x * 128;

    const __half* Kg0 = g_kh + (size_t)bh * S_ * 64;
    const __half* Vg0 = g_vh + (size_t)bh * S_ * 64;

    // --- prologue: Q (128 rows), kv-buffers 0 and 1 (128 kv rows each) ---
    {
        const __half* Qg = g_qh + ((size_t)bh * S_ + q0) * 64;
        #pragma unroll
        for (int i = 0; i < 8; i++) {
            int idx = tid + 128 * i;
            int r = idx >> 3, ch = idx & 7;
            cpasync16(smq + swa8(r, ch), Qg + (size_t)r * 64 + ch * 8);
        }
        CP_COMMIT();
    }
    #pragma unroll
    for (int pb = 0; pb < 2; pb++) {
        const uint32_t kvb = smb + SMKV + (uint32_t)(pb * 32768);
        const __half* Kg = Kg0 + (size_t)pb * 128 * 64;
        const __half* Vg = Vg0 + (size_t)pb * 128 * 64;
        #pragma unroll
        for (int i = 0; i < 8; i++) {
            int idx = tid + 128 * i;
            int r = idx >> 3, ch = idx & 7;
            uint32_t d = swa8(r, ch);
            cpasync16(kvb + d,         Kg + (size_t)r * 64 + ch * 8);
            cpasync16(kvb + 16384 + d, Vg + (size_t)r * 64 + ch * 8);
        }
        CP_COMMIT();
    }

    // fragment lane constants
    const int arow  = (w << 4) + (l & 15);
    const int achnk = l >> 4;
    const int krow  = (l & 7) + ((l >> 4) << 3);
    const int kchnk = (l >> 3) & 1;
    const int vchnk = l >> 4;

    // --- hoist Q fragments (both sets) into registers ---
    CP_WAIT2();
    __syncthreads();
    uint32_t qf[2][4][4];
    #pragma unroll
    for (int st = 0; st < 2; st++)
        #pragma unroll
        for (int ks = 0; ks < 4; ks++)
            ldsm4(qf[st][ks], smq + swa8(st * 64 + arow, ks * 2 + achnk));

    float o[2][8][4];
    #pragma unroll
    for (int st = 0; st < 2; st++)
        #pragma unroll
        for (int i = 0; i < 8; i++)
            #pragma unroll
            for (int j = 0; j < 4; j++) o[st][i][j] = 0.0f;
    // fp32 row-sum accumulators: [set][row-half]
    float lsum[2][2] = {{0.0f, 0.0f}, {0.0f, 0.0f}};

    for (int t = 0; t < NT_; t++) {
        CP_WAIT1();          // kv buffer t resident
        __syncthreads();     // all warps past compute(t-1)
        if (t + 2 < NT_) {
            const uint32_t kvb = smb + SMKV + (uint32_t)(((t + 2) % 3) * 32768);
            const __half* Kg = Kg0 + (size_t)(t + 2) * 128 * 64;
            const __half* Vg = Vg0 + (size_t)(t + 2) * 128 * 64;
            #pragma unroll
            for (int i = 0; i < 8; i++) {
                int idx = tid + 128 * i;
                int r = idx >> 3, ch = idx & 7;
                uint32_t d = swa8(r, ch);
                cpasync16(kvb + d,         Kg + (size_t)r * 64 + ch * 8);
                cpasync16(kvb + 16384 + d, Vg + (size_t)r * 64 + ch * 8);
            }
        }
        CP_COMMIT();

        const uint32_t kvb = smb + SMKV + (uint32_t)((t % 3) * 32768);

        #pragma unroll
        for (int sub = 0; sub < 2; sub++) {
            const uint32_t smk = kvb + (uint32_t)(sub * 8192);
            const uint32_t smv = kvb + 16384 + (uint32_t)(sub * 8192);

            // ---- S = Q.K^T for both q-sets, K fragments loaded once ----
            float s0[8][4], s1[8][4];
            #pragma unroll
            for (int i = 0; i < 8; i++)
                #pragma unroll
                for (int j = 0; j < 4; j++) { s0[i][j] = 0.0f; s1[i][j] = 0.0f; }

            #pragma unroll
            for (int ks = 0; ks < 4; ks++) {
                #pragma unroll
                for (int np = 0; np < 4; np++) {
                    uint32_t kk[4];
                    ldsm4(kk, smk + swa8(np * 16 + krow, ks * 2 + kchnk));
                    mma16816h(s0[2 * np],     qf[0][ks], kk[0], kk[1]);
                    mma16816h(s0[2 * np + 1], qf[0][ks], kk[2], kk[3]);
                    mma16816h(s1[2 * np],     qf[1][ks], kk[0], kk[1]);
                    mma16816h(s1[2 * np + 1], qf[1][ks], kk[2], kk[3]);
                }
            }

            // ---- exp2 (f16x2), HADD2 row-sums, PV with shared V frags ----
            // f16x2 partial-sum accumulators (per set, per row-half)
            uint32_t hs[2][2] = {{0u, 0u}, {0u, 0u}};
            #pragma unroll
            for (int c = 0; c < 4; c++) {
                uint32_t a0[4], a1[4];
                #pragma unroll
                for (int h = 0; h < 2; h++) {
                    float* p0 = s0[2 * c + h];
                    float* p1 = s1[2 * c + h];
                    a0[2 * h]     = ex2h2(packh(p0[0], p0[1]));
                    a0[2 * h + 1] = ex2h2(packh(p0[2], p0[3]));
                    a1[2 * h]     = ex2h2(packh(p1[0], p1[1]));
                    a1[2 * h + 1] = ex2h2(packh(p1[2], p1[3]));
                }
                hs[0][0] = hadd2(hs[0][0], hadd2(a0[0], a0[2]));
                hs[0][1] = hadd2(hs[0][1], hadd2(a0[1], a0[3]));
                hs[1][0] = hadd2(hs[1][0], hadd2(a1[0], a1[2]));
                hs[1][1] = hadd2(hs[1][1], hadd2(a1[1], a1[3]));

                const int vrow = c * 16 + (l & 15);
                #pragma unroll
                for (int j = 0; j < 4; j++) {
                    uint32_t vv[4];
                    ldsm4t(vv, smv + swa8(vrow, 2 * j + vchnk));
                    mma16816h(o[0][2 * j],     a0, vv[0], vv[1]);
                    mma16816h(o[0][2 * j + 1], a0, vv[2], vv[3]);
                    mma16816h(o[1][2 * j],     a1, vv[0], vv[1]);
                    mma16816h(o[1][2 * j + 1], a1, vv[2], vv[3]);
                }
            }
            // drain f16x2 partials into fp32 (max 8 fp16 adds deep)
            #pragma unroll
            for (int st = 0; st < 2; st++)
                #pragma unroll
                for (int rh = 0; rh < 2; rh++) {
                    float2 f = h22f2(hs[st][rh]);
                    lsum[st][rh] += f.x + f.y;
                }
        }
    }

    // ---- epilogue: reduce row sums across the 4 lanes of each row ----
    #pragma unroll
    for (int st = 0; st < 2; st++)
        #pragma unroll
        for (int rh = 0; rh < 2; rh++) {
            lsum[st][rh] += __shfl_xor_sync(0xffffffffu, lsum[st][rh], 1);
            lsum[st][rh] += __shfl_xor_sync(0xffffffffu, lsum[st][rh], 2);
        }

    const int colb = head * HD_ + 2 * (l & 3);
    #pragma unroll
    for (int st = 0; st < 2; st++) {
        const float inv0 = 1.0f / lsum[st][0];
        const float inv1 = 1.0f / lsum[st][1];
        const int row0 = q0 + st * 64 + w * 16 + (l >> 2);
        const int row1 = row0 + 8;
        float* out0 = out + ((size_t)b * S_ + row0) * H_ + colb;
        float* out1 = out + ((size_t)b * S_ + row1) * H_ + colb;
        #pragma unroll
        for (int nt = 0; nt < 8; nt++) {
            *(float2*)(out0 + nt * 8) =
                make_float2(o[st][nt][0] * inv0, o[st][nt][1] * inv0);
            *(float2*)(out1 + nt * 8) =
                make_float2(o[st][nt][2] * inv1, o[st][nt][3] * inv1);
        }
    }
}

// ---------------------------------------------------------------------------
extern "C" void kernel_launch(void* const* d_in, const int* in_sizes, int n_in,
                              void* d_out, int out_size)
{
    (void)in_sizes; (void)n_in; (void)out_size;
    const float* X  = (const float*)d_in[0];
    const float* Wq = (const float*)d_in[1];
    const float* bq = (const float*)d_in[2];
    const float* Wk = (const float*)d_in[3];
    const float* bk = (const float*)d_in[4];
    const float* Wv = (const float*)d_in[5];
    const float* bv = (const float*)d_in[6];
    float* out = (float*)d_out;

    cudaFuncSetAttribute(qkv_mma_kernel,
                         cudaFuncAttributeMaxDynamicSharedMemorySize, GSM_TOT);
    cudaFuncSetAttribute(attn_kernel,
                         cudaFuncAttributeMaxDynamicSharedMemorySize, SMTOT);

    conv_kernel<<<CVX_BLOCKS + 3 * 12 * KB_, 256>>>(X, Wq, Wk, Wv);
    qkv_mma_kernel<<<dim3(H_ / 128, (B_ * S_) / 128, 3), 256, GSM_TOT>>>(bq, bk, bv);
    attn_kernel<<<dim3(S_ / 128, NH_, B_), 128, SMTOT>>>(out);
}

// round 14
// speedup vs baseline: 1.0175x; 1.0175x over previous
#include <cuda_runtime.h>
#include <cuda_fp16.h>
#include <cstdint>

#define B_  2
#define S_  2048
#define H_  768
#define NH_ 12
#define HD_ 64
#define KB_ 12          // 768 / 64 k-chunks

// fp16 projections: [bh][s][64]. Q pre-scaled by log2(e)/8.
__device__ __align__(16) __half g_qh[(size_t)B_ * NH_ * S_ * 64];
__device__ __align__(16) __half g_kh[(size_t)B_ * NH_ * S_ * 64];
__device__ __align__(16) __half g_vh[(size_t)B_ * NH_ * S_ * 64];
// fp16 GEMM inputs:
__device__ __align__(16) __half g_xh[(size_t)B_ * S_ * KB_ * 64];
__device__ __align__(16) __half g_wh[(size_t)3 * H_ * KB_ * 64];

// ============================ PTX helpers ==================================
__device__ __forceinline__ uint32_t smem_u32(const void* p) {
    uint32_t a;
    asm("{ .reg .u64 t; cvta.to.shared.u64 t, %1; cvt.u32.u64 %0, t; }"
        : "=r"(a) : "l"(p));
    return a;
}
__device__ __forceinline__ void cpasync16(uint32_t dst, const void* src) {
    asm volatile("cp.async.cg.shared.global [%0], [%1], 16;"
                 :: "r"(dst), "l"(src) : "memory");
}
#define CP_COMMIT() asm volatile("cp.async.commit_group;" ::: "memory")
#define CP_WAIT0()  asm volatile("cp.async.wait_group 0;" ::: "memory")
#define CP_WAIT1()  asm volatile("cp.async.wait_group 1;" ::: "memory")
#define CP_WAIT2()  asm volatile("cp.async.wait_group 2;" ::: "memory")

__device__ __forceinline__ void ldsm4(uint32_t r[4], uint32_t addr) {
    asm volatile("ldmatrix.sync.aligned.m8n8.x4.shared.b16 {%0,%1,%2,%3}, [%4];"
        : "=r"(r[0]), "=r"(r[1]), "=r"(r[2]), "=r"(r[3]) : "r"(addr));
}
__device__ __forceinline__ void ldsm4t(uint32_t r[4], uint32_t addr) {
    asm volatile("ldmatrix.sync.aligned.m8n8.x4.trans.shared.b16 {%0,%1,%2,%3}, [%4];"
        : "=r"(r[0]), "=r"(r[1]), "=r"(r[2]), "=r"(r[3]) : "r"(addr));
}
// fp16 MMA, fp32 accumulate
__device__ __forceinline__ void mma16816h(float c[4], const uint32_t a[4],
                                          uint32_t b0, uint32_t b1) {
    asm volatile("mma.sync.aligned.m16n8k16.row.col.f32.f16.f16.f32 "
        "{%0,%1,%2,%3}, {%4,%5,%6,%7}, {%8,%9}, {%0,%1,%2,%3};"
        : "+f"(c[0]), "+f"(c[1]), "+f"(c[2]), "+f"(c[3])
        : "r"(a[0]), "r"(a[1]), "r"(a[2]), "r"(a[3]), "r"(b0), "r"(b1));
}
// pack two fp32 -> f16x2 (first arg -> bits [15:0])
__device__ __forceinline__ uint32_t packh(float lo, float hi) {
    uint32_t r; asm("cvt.rn.f16x2.f32 %0, %1, %2;" : "=r"(r) : "f"(hi), "f"(lo));
    return r;
}
// packed fp16x2 exp2
__device__ __forceinline__ uint32_t ex2h2(uint32_t x) {
    uint32_t y; asm("ex2.approx.f16x2 %0, %1;" : "=r"(y) : "r"(x)); return y;
}
// packed fp16x2 add
__device__ __forceinline__ uint32_t hadd2(uint32_t a, uint32_t b) {
    uint32_t y; asm("add.f16x2 %0, %1, %2;" : "=r"(y) : "r"(a), "r"(b)); return y;
}
// unpack f16x2 -> two fp32
__device__ __forceinline__ float2 h22f2(uint32_t h) {
    float lo, hi;
    asm("{ .reg .f16 l, u; mov.b32 {l, u}, %2;\n\t"
        "cvt.f32.f16 %0, l; cvt.f32.f16 %1, u; }"
        : "=f"(lo), "=f"(hi) : "r"(h));
    return make_float2(lo, hi);
}
// 128B rows (64 fp16), 8 chunks of 16B, XOR swizzle -> conflict-free ldmatrix
__device__ __forceinline__ uint32_t swa8(int row, int chunk) {
    return (uint32_t)(row * 128 + ((chunk ^ (row & 7)) << 4));
}

// ---------------------------------------------------------------------------
// Fused conversion kernel (unchanged from R13).
// ---------------------------------------------------------------------------
#define CVX_BLOCKS 1536

__global__ __launch_bounds__(256) void conv_kernel(
    const float* __restrict__ X,
    const float* __restrict__ Wq, const float* __restrict__ Wk,
    const float* __restrict__ Wv)
{
    __shared__ float T[64][65];
    const int tid = threadIdx.x;

    if (blockIdx.x < CVX_BLOCKS) {
        const int t = blockIdx.x * 256 + tid;
        const int m = t / 96, r = t % 96;
        const int kb = r >> 3, p8 = (r & 7) * 8;
        const float* src = X + (size_t)m * H_ + kb * 64 + p8;
        float4 x0 = *(const float4*)(src);
        float4 x1 = *(const float4*)(src + 4);
        uint4 o;
        o.x = packh(x0.x, x0.y);
        o.y = packh(x0.z, x0.w);
        o.z = packh(x1.x, x1.y);
        o.w = packh(x1.z, x1.w);
        *(uint4*)(g_xh + ((size_t)m * KB_ + kb) * 64 + p8) = o;
        return;
    }

    const int i = blockIdx.x - CVX_BLOCKS;
    const int kb = i % KB_;
    const int ng = (i / KB_) % 12;
    const int which = i / (KB_ * 12);
    const float* W = (which == 0) ? Wq : (which == 1) ? Wk : Wv;

    #pragma unroll
    for (int j = 0; j < 16; j++) {
        int idx = tid + 256 * j;
        int r = idx >> 6, c = idx & 63;
        T[r][c] = W[(size_t)(kb * 64 + r) * H_ + ng * 64 + c];
    }
    __syncthreads();

    const int n  = tid >> 2;
    const int jb = tid & 3;
    uint32_t* dst = (uint32_t*)(g_wh +
        (((size_t)which * H_ + ng * 64 + n) * KB_ + kb) * 64);
    #pragma unroll
    for (int j = 0; j < 8; j++) {
        int k2 = jb * 8 + j;
        dst[k2] = packh(T[2 * k2][n], T[2 * k2 + 1][n]);
    }
}

// ---------------------------------------------------------------------------
// fp16 HMMA QKV GEMM (unchanged from R13): 256 thr, tile 128x128, 2 CTAs/SM.
// ---------------------------------------------------------------------------
#define GSM_TOT 98304
#define GBUF    32768

__global__ void __launch_bounds__(256, 2) qkv_mma_kernel(
    const float* __restrict__ bq, const float* __restrict__ bk,
    const float* __restrict__ bv)
{
    extern __shared__ char sm[];
    const uint32_t smb = smem_u32(sm);

    const int tid = threadIdx.x;
    const int l = tid & 31, w = tid >> 5;
    const int wm = w & 3, wn = w >> 2;
    const int which = blockIdx.z;
    const int m0 = blockIdx.y * 128;
    const int n0 = blockIdx.x * 128;

    const __half* Ag = g_xh + (size_t)m0 * KB_ * 64;
    const __half* Bg = g_wh + ((size_t)which * H_ + n0) * KB_ * 64;

    float s[2][8][4];
    #pragma unroll
    for (int mt = 0; mt < 2; mt++)
        #pragma unroll
        for (int nt = 0; nt < 8; nt++)
            #pragma unroll
            for (int j = 0; j < 4; j++) s[mt][nt][j] = 0.0f;

    const int arow0 = 32 * wm + (l & 15);
    const int achnk = l >> 4;
    const int krow  = 64 * wn + (l & 7) + ((l >> 4) << 3);
    const int kchnk = (l >> 3) & 1;

    #pragma unroll
    for (int pb = 0; pb < 2; pb++) {
        const uint32_t off = (uint32_t)(pb * GBUF);
        #pragma unroll
        for (int i = 0; i < 4; i++) {
            int idx = tid + 256 * i;
            int r = idx >> 3, ch = idx & 7;
            cpasync16(smb + off + swa8(r, ch),
                      Ag + ((size_t)r * KB_ + pb) * 64 + ch * 8);
        }
        #pragma unroll
        for (int i = 0; i < 4; i++) {
            int idx = tid + 256 * i;
            int r = idx >> 3, ch = idx & 7;
            cpasync16(smb + off + 16384 + swa8(r, ch),
                      Bg + ((size_t)r * KB_ + pb) * 64 + ch * 8);
        }
        CP_COMMIT();
    }

    for (int kb = 0; kb < KB_; kb++) {
        CP_WAIT1();
        __syncthreads();
        if (kb + 2 < KB_) {
            const uint32_t off = (uint32_t)(((kb + 2) % 3) * GBUF);
            #pragma unroll
            for (int i = 0; i < 4; i++) {
                int idx = tid + 256 * i;
                int r = idx >> 3, ch = idx & 7;
                cpasync16(smb + off + swa8(r, ch),
                          Ag + ((size_t)r * KB_ + kb + 2) * 64 + ch * 8);
            }
            #pragma unroll
            for (int i = 0; i < 4; i++) {
                int idx = tid + 256 * i;
                int r = idx >> 3, ch = idx & 7;
                cpasync16(smb + off + 16384 + swa8(r, ch),
                          Bg + ((size_t)r * KB_ + kb + 2) * 64 + ch * 8);
            }
        }
        CP_COMMIT();

        const uint32_t smA = smb + (uint32_t)((kb % 3) * GBUF);
        const uint32_t smB = smA + 16384;

        #pragma unroll
        for (int ks = 0; ks < 4; ks++) {
            uint32_t a[2][4], bb[4][4];
            #pragma unroll
            for (int mt = 0; mt < 2; mt++)
                ldsm4(a[mt], smA + swa8(arow0 + 16 * mt, ks * 2 + achnk));
            #pragma unroll
            for (int bt = 0; bt < 4; bt++)
                ldsm4(bb[bt], smB + swa8(16 * bt + krow, ks * 2 + kchnk));
            #pragma unroll
            for (int mt = 0; mt < 2; mt++)
                #pragma unroll
                for (int bt = 0; bt < 4; bt++) {
                    mma16816h(s[mt][2 * bt],     a[mt], bb[bt][0], bb[bt][1]);
                    mma16816h(s[mt][2 * bt + 1], a[mt], bb[bt][2], bb[bt][3]);
                }
        }
    }

    const float* bias = (which == 0) ? bq : (which == 1) ? bk : bv;
    __half* Gp = (which == 0) ? g_qh : (which == 1) ? g_kh : g_vh;
    const float sc = (which == 0) ? 0.18033688011112042f : 1.0f;

    const int head = 2 * blockIdx.x + wn;
    #pragma unroll
    for (int mt = 0; mt < 2; mt++) {
        const int r0 = m0 + 32 * wm + 16 * mt + (l >> 2);
        const int b  = r0 >> 11;
        const int s0 = r0 & (S_ - 1);
        const int bh_ = b * NH_ + head;
        uint32_t* d0 = (uint32_t*)(Gp + ((size_t)bh_ * S_ + s0) * 64);
        uint32_t* d1 = (uint32_t*)(Gp + ((size_t)bh_ * S_ + s0 + 8) * 64);
        #pragma unroll
        for (int nt = 0; nt < 8; nt++) {
            const int c0 = 8 * nt + 2 * (l & 3);
            const float b0 = __ldg(bias + head * 64 + c0);
            const float b1 = __ldg(bias + head * 64 + c0 + 1);
            d0[c0 >> 1] = packh((s[mt][nt][0] + b0) * sc, (s[mt][nt][1] + b1) * sc);
            d1[c0 >> 1] = packh((s[mt][nt][2] + b0) * sc, (s[mt][nt][3] + b1) * sc);
        }
    }
}

// ---------------------------------------------------------------------------
// fp16 HMMA flash attention v6: q-tile 128/CTA, kv-tile 64 triple-buffered,
// softmax fused into the np loop (16-kv S chunk -> exp -> PV immediately) so
// only one score chunk is live -> regs fit 3 CTAs/SM. Grid 384 on 444 slots
// = SINGLE WAVE. smem: Q 16KB + 3 x 16KB = 64KB.
// ---------------------------------------------------------------------------
#define SMQ   0
#define SMKV  16384
#define SMTOT 65536
#define NT_   (S_ / 64)

__global__ void __launch_bounds__(128, 3) attn_kernel(float* __restrict__ out)
{
    extern __shared__ char sm[];
    const uint32_t smb = smem_u32(sm);
    const uint32_t smq = smb + SMQ;

    const int tid = threadIdx.x;
    const int l = tid & 31, w = tid >> 5;
    const int head = blockIdx.y, b = blockIdx.z;
    const int bh = b * NH_ + head;
    const int q0 = blockIdx.x * 128;

    const __half* Kg0 = g_kh + (size_t)bh * S_ * 64;
    const __half* Vg0 = g_vh + (size_t)bh * S_ * 64;

    // --- prologue: Q (128 rows), kv-tiles 0 and 1 (64 rows each) ---
    {
        const __half* Qg = g_qh + ((size_t)bh * S_ + q0) * 64;
        #pragma unroll
        for (int i = 0; i < 8; i++) {
            int idx = tid + 128 * i;
            int r = idx >> 3, ch = idx & 7;
            cpasync16(smq + swa8(r, ch), Qg + (size_t)r * 64 + ch * 8);
        }
        CP_COMMIT();
    }
    #pragma unroll
    for (int pb = 0; pb < 2; pb++) {
        const uint32_t kvb = smb + SMKV + (uint32_t)(pb * 16384);
        const __half* Kg = Kg0 + (size_t)pb * 64 * 64;
        const __half* Vg = Vg0 + (size_t)pb * 64 * 64;
        #pragma unroll
        for (int i = 0; i < 4; i++) {
            int idx = tid + 128 * i;
            int r = idx >> 3, ch = idx & 7;
            uint32_t d = swa8(r, ch);
            cpasync16(kvb + d,        Kg + (size_t)r * 64 + ch * 8);
            cpasync16(kvb + 8192 + d, Vg + (size_t)r * 64 + ch * 8);
        }
        CP_COMMIT();
    }

    // fragment lane constants
    const int arow  = (w << 4) + (l & 15);
    const int achnk = l >> 4;
    const int krow  = (l & 7) + ((l >> 4) << 3);
    const int kchnk = (l >> 3) & 1;
    const int vchnk = l >> 4;

    // --- hoist Q fragments (both sets) into registers ---
    CP_WAIT2();
    __syncthreads();
    uint32_t qf[2][4][4];
    #pragma unroll
    for (int st = 0; st < 2; st++)
        #pragma unroll
        for (int ks = 0; ks < 4; ks++)
            ldsm4(qf[st][ks], smq + swa8(st * 64 + arow, ks * 2 + achnk));

    float o[2][8][4];
    #pragma unroll
    for (int st = 0; st < 2; st++)
        #pragma unroll
        for (int i = 0; i < 8; i++)
            #pragma unroll
            for (int j = 0; j < 4; j++) o[st][i][j] = 0.0f;
    // fp32 row-sum accumulators: [set][row-half]
    float lsum[2][2] = {{0.0f, 0.0f}, {0.0f, 0.0f}};

    for (int t = 0; t < NT_; t++) {
        CP_WAIT1();          // kv tile t resident
        __syncthreads();     // all warps past compute(t-1)
        if (t + 2 < NT_) {
            const uint32_t kvb = smb + SMKV + (uint32_t)(((t + 2) % 3) * 16384);
            const __half* Kg = Kg0 + (size_t)(t + 2) * 64 * 64;
            const __half* Vg = Vg0 + (size_t)(t + 2) * 64 * 64;
            #pragma unroll
            for (int i = 0; i < 4; i++) {
                int idx = tid + 128 * i;
                int r = idx >> 3, ch = idx & 7;
                uint32_t d = swa8(r, ch);
                cpasync16(kvb + d,        Kg + (size_t)r * 64 + ch * 8);
                cpasync16(kvb + 8192 + d, Vg + (size_t)r * 64 + ch * 8);
            }
        }
        CP_COMMIT();

        const uint32_t smk = smb + SMKV + (uint32_t)((t % 3) * 16384);
        const uint32_t smv = smk + 8192;

        // f16x2 partial row-sum accumulators for this tile
        uint32_t hs[2][2] = {{0u, 0u}, {0u, 0u}};

        // ---- per 16-kv chunk: S -> exp -> PV (one chunk of scores live) ----
        #pragma unroll
        for (int np = 0; np < 4; np++) {
            float s0[2][4], s1[2][4];
            #pragma unroll
            for (int h = 0; h < 2; h++)
                #pragma unroll
                for (int j = 0; j < 4; j++) { s0[h][j] = 0.0f; s1[h][j] = 0.0f; }

            #pragma unroll
            for (int ks = 0; ks < 4; ks++) {
                uint32_t kk[4];
                ldsm4(kk, smk + swa8(np * 16 + krow, ks * 2 + kchnk));
                mma16816h(s0[0], qf[0][ks], kk[0], kk[1]);
                mma16816h(s0[1], qf[0][ks], kk[2], kk[3]);
                mma16816h(s1[0], qf[1][ks], kk[0], kk[1]);
                mma16816h(s1[1], qf[1][ks], kk[2], kk[3]);
            }

            uint32_t a0[4], a1[4];
            #pragma unroll
            for (int h = 0; h < 2; h++) {
                a0[2 * h]     = ex2h2(packh(s0[h][0], s0[h][1]));
                a0[2 * h + 1] = ex2h2(packh(s0[h][2], s0[h][3]));
                a1[2 * h]     = ex2h2(packh(s1[h][0], s1[h][1]));
                a1[2 * h + 1] = ex2h2(packh(s1[h][2], s1[h][3]));
            }
            hs[0][0] = hadd2(hs[0][0], hadd2(a0[0], a0[2]));
            hs[0][1] = hadd2(hs[0][1], hadd2(a0[1], a0[3]));
            hs[1][0] = hadd2(hs[1][0], hadd2(a1[0], a1[2]));
            hs[1][1] = hadd2(hs[1][1], hadd2(a1[1], a1[3]));

            const int vrow = np * 16 + (l & 15);
            #pragma unroll
            for (int j = 0; j < 4; j++) {
                uint32_t vv[4];
                ldsm4t(vv, smv + swa8(vrow, 2 * j + vchnk));
                mma16816h(o[0][2 * j],     a0, vv[0], vv[1]);
                mma16816h(o[0][2 * j + 1], a0, vv[2], vv[3]);
                mma16816h(o[1][2 * j],     a1, vv[0], vv[1]);
                mma16816h(o[1][2 * j + 1], a1, vv[2], vv[3]);
            }
        }

        // drain f16x2 partials into fp32 (max 8 fp16 adds deep)
        #pragma unroll
        for (int st = 0; st < 2; st++)
            #pragma unroll
            for (int rh = 0; rh < 2; rh++) {
                float2 f = h22f2(hs[st][rh]);
                lsum[st][rh] += f.x + f.y;
            }
    }

    // ---- epilogue: reduce row sums across the 4 lanes of each row ----
    #pragma unroll
    for (int st = 0; st < 2; st++)
        #pragma unroll
        for (int rh = 0; rh < 2; rh++) {
            lsum[st][rh] += __shfl_xor_sync(0xffffffffu, lsum[st][rh], 1);
            lsum[st][rh] += __shfl_xor_sync(0xffffffffu, lsum[st][rh], 2);
        }

    const int colb = head * HD_ + 2 * (l & 3);
    #pragma unroll
    for (int st = 0; st < 2; st++) {
        const float inv0 = 1.0f / lsum[st][0];
        const float inv1 = 1.0f / lsum[st][1];
        const int row0 = q0 + st * 64 + w * 16 + (l >> 2);
        const int row1 = row0 + 8;
        float* out0 = out + ((size_t)b * S_ + row0) * H_ + colb;
        float* out1 = out + ((size_t)b * S_ + row1) * H_ + colb;
        #pragma unroll
        for (int nt = 0; nt < 8; nt++) {
            *(float2*)(out0 + nt * 8) =
                make_float2(o[st][nt][0] * inv0, o[st][nt][1] * inv0);
            *(float2*)(out1 + nt * 8) =
                make_float2(o[st][nt][2] * inv1, o[st][nt][3] * inv1);
        }
    }
}

// ---------------------------------------------------------------------------
extern "C" void kernel_launch(void* const* d_in, const int* in_sizes, int n_in,
                              void* d_out, int out_size)
{
    (void)in_sizes; (void)n_in; (void)out_size;
    const float* X  = (const float*)d_in[0];
    const float* Wq = (const float*)d_in[1];
    const float* bq = (const float*)d_in[2];
    const float* Wk = (const float*)d_in[3];
    const float* bk = (const float*)d_in[4];
    const float* Wv = (const float*)d_in[5];
    const float* bv = (const float*)d_in[6];
    float* out = (float*)d_out;

    cudaFuncSetAttribute(qkv_mma_kernel,
                         cudaFuncAttributeMaxDynamicSharedMemorySize, GSM_TOT);
    cudaFuncSetAttribute(attn_kernel,
                         cudaFuncAttributeMaxDynamicSharedMemorySize, SMTOT);

    conv_kernel<<<CVX_BLOCKS + 3 * 12 * KB_, 256>>>(X, Wq, Wk, Wv);
    qkv_mma_kernel<<<dim3(H_ / 128, (B_ * S_) / 128, 3), 256, GSM_TOT>>>(bq, bk, bv);
    attn_kernel<<<dim3(S_ / 128, NH_, B_), 128, SMTOT>>>(out);
}

// round 15
// speedup vs baseline: 1.0178x; 1.0003x over previous
#include <cuda_runtime.h>
#include <cuda_fp16.h>
#include <cstdint>

#define B_  2
#define S_  2048
#define H_  768
#define NH_ 12
#define HD_ 64
#define KB_ 12          // 768 / 64 k-chunks

// fp16 projections: [bh][s][64]. Q pre-scaled by log2(e)/8.
__device__ __align__(16) __half g_qh[(size_t)B_ * NH_ * S_ * 64];
__device__ __align__(16) __half g_kh[(size_t)B_ * NH_ * S_ * 64];
__device__ __align__(16) __half g_vh[(size_t)B_ * NH_ * S_ * 64];
// fp16 GEMM inputs:
__device__ __align__(16) __half g_xh[(size_t)B_ * S_ * KB_ * 64];
__device__ __align__(16) __half g_wh[(size_t)3 * H_ * KB_ * 64];

// ============================ PTX helpers ==================================
__device__ __forceinline__ uint32_t smem_u32(const void* p) {
    uint32_t a;
    asm("{ .reg .u64 t; cvta.to.shared.u64 t, %1; cvt.u32.u64 %0, t; }"
        : "=r"(a) : "l"(p));
    return a;
}
__device__ __forceinline__ void cpasync16(uint32_t dst, const void* src) {
    asm volatile("cp.async.cg.shared.global [%0], [%1], 16;"
                 :: "r"(dst), "l"(src) : "memory");
}
#define CP_COMMIT() asm volatile("cp.async.commit_group;" ::: "memory")
#define CP_WAIT0()  asm volatile("cp.async.wait_group 0;" ::: "memory")
#define CP_WAIT1()  asm volatile("cp.async.wait_group 1;" ::: "memory")
#define CP_WAIT2()  asm volatile("cp.async.wait_group 2;" ::: "memory")

__device__ __forceinline__ void ldsm4(uint32_t r[4], uint32_t addr) {
    asm volatile("ldmatrix.sync.aligned.m8n8.x4.shared.b16 {%0,%1,%2,%3}, [%4];"
        : "=r"(r[0]), "=r"(r[1]), "=r"(r[2]), "=r"(r[3]) : "r"(addr));
}
__device__ __forceinline__ void ldsm4t(uint32_t r[4], uint32_t addr) {
    asm volatile("ldmatrix.sync.aligned.m8n8.x4.trans.shared.b16 {%0,%1,%2,%3}, [%4];"
        : "=r"(r[0]), "=r"(r[1]), "=r"(r[2]), "=r"(r[3]) : "r"(addr));
}
// fp16 MMA, fp32 accumulate
__device__ __forceinline__ void mma16816h(float c[4], const uint32_t a[4],
                                          uint32_t b0, uint32_t b1) {
    asm volatile("mma.sync.aligned.m16n8k16.row.col.f32.f16.f16.f32 "
        "{%0,%1,%2,%3}, {%4,%5,%6,%7}, {%8,%9}, {%0,%1,%2,%3};"
        : "+f"(c[0]), "+f"(c[1]), "+f"(c[2]), "+f"(c[3])
        : "r"(a[0]), "r"(a[1]), "r"(a[2]), "r"(a[3]), "r"(b0), "r"(b1));
}
// fp16 MMA, fp16 accumulate (D/C packed f16x2: reg0 = row r cols(2l,2l+1),
// reg1 = row r+8 cols(2l,2l+1))
__device__ __forceinline__ void mma16816hh(uint32_t c[2], const uint32_t a[4],
                                           uint32_t b0, uint32_t b1) {
    asm volatile("mma.sync.aligned.m16n8k16.row.col.f16.f16.f16.f16 "
        "{%0,%1}, {%2,%3,%4,%5}, {%6,%7}, {%0,%1};"
        : "+r"(c[0]), "+r"(c[1])
        : "r"(a[0]), "r"(a[1]), "r"(a[2]), "r"(a[3]), "r"(b0), "r"(b1));
}
// pack two fp32 -> f16x2 (first arg -> bits [15:0])
__device__ __forceinline__ uint32_t packh(float lo, float hi) {
    uint32_t r; asm("cvt.rn.f16x2.f32 %0, %1, %2;" : "=r"(r) : "f"(hi), "f"(lo));
    return r;
}
// packed fp16x2 exp2
__device__ __forceinline__ uint32_t ex2h2(uint32_t x) {
    uint32_t y; asm("ex2.approx.f16x2 %0, %1;" : "=r"(y) : "r"(x)); return y;
}
// packed fp16x2 add
__device__ __forceinline__ uint32_t hadd2(uint32_t a, uint32_t b) {
    uint32_t y; asm("add.f16x2 %0, %1, %2;" : "=r"(y) : "r"(a), "r"(b)); return y;
}
// unpack f16x2 -> two fp32
__device__ __forceinline__ float2 h22f2(uint32_t h) {
    float lo, hi;
    asm("{ .reg .f16 l, u; mov.b32 {l, u}, %2;\n\t"
        "cvt.f32.f16 %0, l; cvt.f32.f16 %1, u; }"
        : "=f"(lo), "=f"(hi) : "r"(h));
    return make_float2(lo, hi);
}
// 128B rows (64 fp16), 8 chunks of 16B, XOR swizzle -> conflict-free ldmatrix
__device__ __forceinline__ uint32_t swa8(int row, int chunk) {
    return (uint32_t)(row * 128 + ((chunk ^ (row & 7)) << 4));
}

// ---------------------------------------------------------------------------
// Fused conversion kernel (unchanged).
// ---------------------------------------------------------------------------
#define CVX_BLOCKS 1536

__global__ __launch_bounds__(256) void conv_kernel(
    const float* __restrict__ X,
    const float* __restrict__ Wq, const float* __restrict__ Wk,
    const float* __restrict__ Wv)
{
    __shared__ float T[64][65];
    const int tid = threadIdx.x;

    if (blockIdx.x < CVX_BLOCKS) {
        const int t = blockIdx.x * 256 + tid;
        const int m = t / 96, r = t % 96;
        const int kb = r >> 3, p8 = (r & 7) * 8;
        const float* src = X + (size_t)m * H_ + kb * 64 + p8;
        float4 x0 = *(const float4*)(src);
        float4 x1 = *(const float4*)(src + 4);
        uint4 o;
        o.x = packh(x0.x, x0.y);
        o.y = packh(x0.z, x0.w);
        o.z = packh(x1.x, x1.y);
        o.w = packh(x1.z, x1.w);
        *(uint4*)(g_xh + ((size_t)m * KB_ + kb) * 64 + p8) = o;
        return;
    }

    const int i = blockIdx.x - CVX_BLOCKS;
    const int kb = i % KB_;
    const int ng = (i / KB_) % 12;
    const int which = i / (KB_ * 12);
    const float* W = (which == 0) ? Wq : (which == 1) ? Wk : Wv;

    #pragma unroll
    for (int j = 0; j < 16; j++) {
        int idx = tid + 256 * j;
        int r = idx >> 6, c = idx & 63;
        T[r][c] = W[(size_t)(kb * 64 + r) * H_ + ng * 64 + c];
    }
    __syncthreads();

    const int n  = tid >> 2;
    const int jb = tid & 3;
    uint32_t* dst = (uint32_t*)(g_wh +
        (((size_t)which * H_ + ng * 64 + n) * KB_ + kb) * 64);
    #pragma unroll
    for (int j = 0; j < 8; j++) {
        int k2 = jb * 8 + j;
        dst[k2] = packh(T[2 * k2][n], T[2 * k2 + 1][n]);
    }
}

// ---------------------------------------------------------------------------
// fp16 HMMA QKV GEMM (unchanged): 256 thr, tile 128x128, 2 CTAs/SM.
// ---------------------------------------------------------------------------
#define GSM_TOT 98304
#define GBUF    32768

__global__ void __launch_bounds__(256, 2) qkv_mma_kernel(
    const float* __restrict__ bq, const float* __restrict__ bk,
    const float* __restrict__ bv)
{
    extern __shared__ char sm[];
    const uint32_t smb = smem_u32(sm);

    const int tid = threadIdx.x;
    const int l = tid & 31, w = tid >> 5;
    const int wm = w & 3, wn = w >> 2;
    const int which = blockIdx.z;
    const int m0 = blockIdx.y * 128;
    const int n0 = blockIdx.x * 128;

    const __half* Ag = g_xh + (size_t)m0 * KB_ * 64;
    const __half* Bg = g_wh + ((size_t)which * H_ + n0) * KB_ * 64;

    float s[2][8][4];
    #pragma unroll
    for (int mt = 0; mt < 2; mt++)
        #pragma unroll
        for (int nt = 0; nt < 8; nt++)
            #pragma unroll
            for (int j = 0; j < 4; j++) s[mt][nt][j] = 0.0f;

    const int arow0 = 32 * wm + (l & 15);
    const int achnk = l >> 4;
    const int krow  = 64 * wn + (l & 7) + ((l >> 4) << 3);
    const int kchnk = (l >> 3) & 1;

    #pragma unroll
    for (int pb = 0; pb < 2; pb++) {
        const uint32_t off = (uint32_t)(pb * GBUF);
        #pragma unroll
        for (int i = 0; i < 4; i++) {
            int idx = tid + 256 * i;
            int r = idx >> 3, ch = idx & 7;
            cpasync16(smb + off + swa8(r, ch),
                      Ag + ((size_t)r * KB_ + pb) * 64 + ch * 8);
        }
        #pragma unroll
        for (int i = 0; i < 4; i++) {
            int idx = tid + 256 * i;
            int r = idx >> 3, ch = idx & 7;
            cpasync16(smb + off + 16384 + swa8(r, ch),
                      Bg + ((size_t)r * KB_ + pb) * 64 + ch * 8);
        }
        CP_COMMIT();
    }

    for (int kb = 0; kb < KB_; kb++) {
        CP_WAIT1();
        __syncthreads();
        if (kb + 2 < KB_) {
            const uint32_t off = (uint32_t)(((kb + 2) % 3) * GBUF);
            #pragma unroll
            for (int i = 0; i < 4; i++) {
                int idx = tid + 256 * i;
                int r = idx >> 3, ch = idx & 7;
                cpasync16(smb + off + swa8(r, ch),
                          Ag + ((size_t)r * KB_ + kb + 2) * 64 + ch * 8);
            }
            #pragma unroll
            for (int i = 0; i < 4; i++) {
                int idx = tid + 256 * i;
                int r = idx >> 3, ch = idx & 7;
                cpasync16(smb + off + 16384 + swa8(r, ch),
                          Bg + ((size_t)r * KB_ + kb + 2) * 64 + ch * 8);
            }
        }
        CP_COMMIT();

        const uint32_t smA = smb + (uint32_t)((kb % 3) * GBUF);
        const uint32_t smB = smA + 16384;

        #pragma unroll
        for (int ks = 0; ks < 4; ks++) {
            uint32_t a[2][4], bb[4][4];
            #pragma unroll
            for (int mt = 0; mt < 2; mt++)
                ldsm4(a[mt], smA + swa8(arow0 + 16 * mt, ks * 2 + achnk));
            #pragma unroll
            for (int bt = 0; bt < 4; bt++)
                ldsm4(bb[bt], smB + swa8(16 * bt + krow, ks * 2 + kchnk));
            #pragma unroll
            for (int mt = 0; mt < 2; mt++)
                #pragma unroll
                for (int bt = 0; bt < 4; bt++) {
                    mma16816h(s[mt][2 * bt],     a[mt], bb[bt][0], bb[bt][1]);
                    mma16816h(s[mt][2 * bt + 1], a[mt], bb[bt][2], bb[bt][3]);
                }
        }
    }

    const float* bias = (which == 0) ? bq : (which == 1) ? bk : bv;
    __half* Gp = (which == 0) ? g_qh : (which == 1) ? g_kh : g_vh;
    const float sc = (which == 0) ? 0.18033688011112042f : 1.0f;

    const int head = 2 * blockIdx.x + wn;
    #pragma unroll
    for (int mt = 0; mt < 2; mt++) {
        const int r0 = m0 + 32 * wm + 16 * mt + (l >> 2);
        const int b  = r0 >> 11;
        const int s0 = r0 & (S_ - 1);
        const int bh_ = b * NH_ + head;
        uint32_t* d0 = (uint32_t*)(Gp + ((size_t)bh_ * S_ + s0) * 64);
        uint32_t* d1 = (uint32_t*)(Gp + ((size_t)bh_ * S_ + s0 + 8) * 64);
        #pragma unroll
        for (int nt = 0; nt < 8; nt++) {
            const int c0 = 8 * nt + 2 * (l & 3);
            const float b0 = __ldg(bias + head * 64 + c0);
            const float b1 = __ldg(bias + head * 64 + c0 + 1);
            d0[c0 >> 1] = packh((s[mt][nt][0] + b0) * sc, (s[mt][nt][1] + b1) * sc);
            d1[c0 >> 1] = packh((s[mt][nt][2] + b0) * sc, (s[mt][nt][3] + b1) * sc);
        }
    }
}

// ---------------------------------------------------------------------------
// fp16 HMMA flash attention v7: QK S-GEMM in fp16-ACCUMULATE MMAs (packed
// f16x2 accumulators = PV A-fragment layout, zero packh; 2x rate if f16-acc
// is full-rate). q-tile 128/CTA, kv-tile 64 triple-buffered, fused
// per-16kv-chunk softmax, PV fp32-acc. smem 64KB; 3 CTAs/SM, single wave.
// ---------------------------------------------------------------------------
#define SMQ   0
#define SMKV  16384
#define SMTOT 65536
#define NT_   (S_ / 64)

__global__ void __launch_bounds__(128, 3) attn_kernel(float* __restrict__ out)
{
    extern __shared__ char sm[];
    const uint32_t smb = smem_u32(sm);
    const uint32_t smq = smb + SMQ;

    const int tid = threadIdx.x;
    const int l = tid & 31, w = tid >> 5;
    const int head = blockIdx.y, b = blockIdx.z;
    const int bh = b * NH_ + head;
    const int q0 = blockIdx.x * 128;

    const __half* Kg0 = g_kh + (size_t)bh * S_ * 64;
    const __half* Vg0 = g_vh + (size_t)bh * S_ * 64;

    // --- prologue: Q (128 rows), kv-tiles 0 and 1 (64 rows each) ---
    {
        const __half* Qg = g_qh + ((size_t)bh * S_ + q0) * 64;
        #pragma unroll
        for (int i = 0; i < 8; i++) {
            int idx = tid + 128 * i;
            int r = idx >> 3, ch = idx & 7;
            cpasync16(smq + swa8(r, ch), Qg + (size_t)r * 64 + ch * 8);
        }
        CP_COMMIT();
    }
    #pragma unroll
    for (int pb = 0; pb < 2; pb++) {
        const uint32_t kvb = smb + SMKV + (uint32_t)(pb * 16384);
        const __half* Kg = Kg0 + (size_t)pb * 64 * 64;
        const __half* Vg = Vg0 + (size_t)pb * 64 * 64;
        #pragma unroll
        for (int i = 0; i < 4; i++) {
            int idx = tid + 128 * i;
            int r = idx >> 3, ch = idx & 7;
            uint32_t d = swa8(r, ch);
            cpasync16(kvb + d,        Kg + (size_t)r * 64 + ch * 8);
            cpasync16(kvb + 8192 + d, Vg + (size_t)r * 64 + ch * 8);
        }
        CP_COMMIT();
    }

    // fragment lane constants
    const int arow  = (w << 4) + (l & 15);
    const int achnk = l >> 4;
    const int krow  = (l & 7) + ((l >> 4) << 3);
    const int kchnk = (l >> 3) & 1;
    const int vchnk = l >> 4;

    // --- hoist Q fragments (both sets) into registers ---
    CP_WAIT2();
    __syncthreads();
    uint32_t qf[2][4][4];
    #pragma unroll
    for (int st = 0; st < 2; st++)
        #pragma unroll
        for (int ks = 0; ks < 4; ks++)
            ldsm4(qf[st][ks], smq + swa8(st * 64 + arow, ks * 2 + achnk));

    float o[2][8][4];
    #pragma unroll
    for (int st = 0; st < 2; st++)
        #pragma unroll
        for (int i = 0; i < 8; i++)
            #pragma unroll
            for (int j = 0; j < 4; j++) o[st][i][j] = 0.0f;
    // fp32 row-sum accumulators: [set][row-half]
    float lsum[2][2] = {{0.0f, 0.0f}, {0.0f, 0.0f}};

    for (int t = 0; t < NT_; t++) {
        CP_WAIT1();          // kv tile t resident
        __syncthreads();     // all warps past compute(t-1)
        if (t + 2 < NT_) {
            const uint32_t kvb = smb + SMKV + (uint32_t)(((t + 2) % 3) * 16384);
            const __half* Kg = Kg0 + (size_t)(t + 2) * 64 * 64;
            const __half* Vg = Vg0 + (size_t)(t + 2) * 64 * 64;
            #pragma unroll
            for (int i = 0; i < 4; i++) {
                int idx = tid + 128 * i;
                int r = idx >> 3, ch = idx & 7;
                uint32_t d = swa8(r, ch);
                cpasync16(kvb + d,        Kg + (size_t)r * 64 + ch * 8);
                cpasync16(kvb + 8192 + d, Vg + (size_t)r * 64 + ch * 8);
            }
        }
        CP_COMMIT();

        const uint32_t smk = smb + SMKV + (uint32_t)((t % 3) * 16384);
        const uint32_t smv = smk + 8192;

        // f16x2 partial row-sum accumulators for this tile
        uint32_t hs[2][2] = {{0u, 0u}, {0u, 0u}};

        // ---- per 16-kv chunk: S (f16 acc) -> exp -> PV (fp32 acc) ----
        #pragma unroll
        for (int np = 0; np < 4; np++) {
            // S accumulators: [set][ntile][row-half], packed f16x2, zeroed
            uint32_t s0[2][2] = {{0u, 0u}, {0u, 0u}};
            uint32_t s1[2][2] = {{0u, 0u}, {0u, 0u}};

            #pragma unroll
            for (int ks = 0; ks < 4; ks++) {
                uint32_t kk[4];
                ldsm4(kk, smk + swa8(np * 16 + krow, ks * 2 + kchnk));
                mma16816hh(s0[0], qf[0][ks], kk[0], kk[1]);
                mma16816hh(s0[1], qf[0][ks], kk[2], kk[3]);
                mma16816hh(s1[0], qf[1][ks], kk[0], kk[1]);
                mma16816hh(s1[1], qf[1][ks], kk[2], kk[3]);
            }

            // exp2 directly on packed f16x2 accumulators (already in PV
            // A-fragment layout: a[2h] = ntile h row r, a[2h+1] = row r+8)
            uint32_t a0[4], a1[4];
            #pragma unroll
            for (int h = 0; h < 2; h++) {
                a0[2 * h]     = ex2h2(s0[h][0]);
                a0[2 * h + 1] = ex2h2(s0[h][1]);
                a1[2 * h]     = ex2h2(s1[h][0]);
                a1[2 * h + 1] = ex2h2(s1[h][1]);
            }
            hs[0][0] = hadd2(hs[0][0], hadd2(a0[0], a0[2]));
            hs[0][1] = hadd2(hs[0][1], hadd2(a0[1], a0[3]));
            hs[1][0] = hadd2(hs[1][0], hadd2(a1[0], a1[2]));
            hs[1][1] = hadd2(hs[1][1], hadd2(a1[1], a1[3]));

            const int vrow = np * 16 + (l & 15);
            #pragma unroll
            for (int j = 0; j < 4; j++) {
                uint32_t vv[4];
                ldsm4t(vv, smv + swa8(vrow, 2 * j + vchnk));
                mma16816h(o[0][2 * j],     a0, vv[0], vv[1]);
                mma16816h(o[0][2 * j + 1], a0, vv[2], vv[3]);
                mma16816h(o[1][2 * j],     a1, vv[0], vv[1]);
                mma16816h(o[1][2 * j + 1], a1, vv[2], vv[3]);
            }
        }

        // drain f16x2 partials into fp32 (max 8 fp16 adds deep)
        #pragma unroll
        for (int st = 0; st < 2; st++)
            #pragma unroll
            for (int rh = 0; rh < 2; rh++) {
                float2 f = h22f2(hs[st][rh]);
                lsum[st][rh] += f.x + f.y;
            }
    }

    // ---- epilogue: reduce row sums across the 4 lanes of each row ----
    #pragma unroll
    for (int st = 0; st < 2; st++)
        #pragma unroll
        for (int rh = 0; rh < 2; rh++) {
            lsum[st][rh] += __shfl_xor_sync(0xffffffffu, lsum[st][rh], 1);
            lsum[st][rh] += __shfl_xor_sync(0xffffffffu, lsum[st][rh], 2);
        }

    const int colb = head * HD_ + 2 * (l & 3);
    #pragma unroll
    for (int st = 0; st < 2; st++) {
        const float inv0 = 1.0f / lsum[st][0];
        const float inv1 = 1.0f / lsum[st][1];
        const int row0 = q0 + st * 64 + w * 16 + (l >> 2);
        const int row1 = row0 + 8;
        float* out0 = out + ((size_t)b * S_ + row0) * H_ + colb;
        float* out1 = out + ((size_t)b * S_ + row1) * H_ + colb;
        #pragma unroll
        for (int nt = 0; nt < 8; nt++) {
            *(float2*)(out0 + nt * 8) =
                make_float2(o[st][nt][0] * inv0, o[st][nt][1] * inv0);
            *(float2*)(out1 + nt * 8) =
                make_float2(o[st][nt][2] * inv1, o[st][nt][3] * inv1);
        }
    }
}

// ---------------------------------------------------------------------------
extern "C" void kernel_launch(void* const* d_in, const int* in_sizes, int n_in,
                              void* d_out, int out_size)
{
    (void)in_sizes; (void)n_in; (void)out_size;
    const float* X  = (const float*)d_in[0];
    const float* Wq = (const float*)d_in[1];
    const float* bq = (const float*)d_in[2];
    const float* Wk = (const float*)d_in[3];
    const float* bk = (const float*)d_in[4];
    const float* Wv = (const float*)d_in[5];
    const float* bv = (const float*)d_in[6];
    float* out = (float*)d_out;

    cudaFuncSetAttribute(qkv_mma_kernel,
                         cudaFuncAttributeMaxDynamicSharedMemorySize, GSM_TOT);
    cudaFuncSetAttribute(attn_kernel,
                         cudaFuncAttributeMaxDynamicSharedMemorySize, SMTOT);

    conv_kernel<<<CVX_BLOCKS + 3 * 12 * KB_, 256>>>(X, Wq, Wk, Wv);
    qkv_mma_kernel<<<dim3(H_ / 128, (B_ * S_) / 128, 3), 256, GSM_TOT>>>(bq, bk, bv);
    attn_kernel<<<dim3(S_ / 128, NH_, B_), 128, SMTOT>>>(out);
}